// round 1
// baseline (speedup 1.0000x reference)
#include <cuda_runtime.h>

#define TILE   256
#define FLEN   16
#define BATCH  64
#define T8     1038
#define NNODES 256

// Max level-output element count is level 8: 64*256*1038 = 17,006,592 floats.
#define BUF_ELEMS 17006592

__device__ float g_bufA[BUF_ELEMS];
__device__ float g_bufB[BUF_ELEMS];

// db8 decomposition low-pass filter, reversed (rev(DEC_LO)[i] = DEC_LO[15-i])
__constant__ float c_lo[16] = {
     0.0018899503327594609f, -0.0003029205147213668f, -0.01495225833704823f,
     0.003808752013890615f,   0.049137179673607506f,  -0.027219029917056003f,
    -0.05194583810770904f,    0.3644418948353314f,     0.7771857517005235f,
     0.4813596512583722f,    -0.061273359067658524f,  -0.1432942383508097f,
     0.007607487324917605f,   0.03169508781149298f,   -0.0005421323317911481f,
    -0.0033824159510061256f
};
// reversed high-pass = (-1)^i * DEC_LO[i]
__constant__ float c_hi[16] = {
    -0.0033824159510061256f,  0.0005421323317911481f,  0.03169508781149298f,
    -0.007607487324917605f,  -0.1432942383508097f,     0.061273359067658524f,
     0.4813596512583722f,    -0.7771857517005235f,     0.3644418948353314f,
     0.05194583810770904f,   -0.027219029917056003f,  -0.049137179673607506f,
     0.003808752013890615f,   0.01495225833704823f,   -0.0003029205147213668f,
    -0.0018899503327594609f
};

// One DWT level: rows = BATCH * n_in signals of length t_in.
// Each block handles TILE consecutive output samples of one row, producing
// both the low-pass and high-pass child rows.
// in_sel: 0 = external input ptr, 1 = g_bufA, 2 = g_bufB.  out_sel: 1 or 2.
__global__ void dwt_level_kernel(const float* __restrict__ ext_in,
                                 int in_sel, int out_sel,
                                 int n_in, int t_in, int t_out) {
    __shared__ float s[2 * TILE + FLEN - 2];   // 526 floats

    const float* in  = (in_sel == 0) ? ext_in : (in_sel == 1 ? g_bufA : g_bufB);
    float*       out = (out_sel == 1) ? g_bufA : g_bufB;

    int row = blockIdx.y;                       // 0 .. BATCH*n_in-1
    int k0  = blockIdx.x * TILE;
    const float* src = in + (long long)row * t_in;

    // Load padded window: padded index j = 2*k0 + i, signal index = j - 14 (reflect)
    int jbase = 2 * k0 - 14;
    for (int i = threadIdx.x; i < 2 * TILE + FLEN - 2; i += blockDim.x) {
        int idx = jbase + i;
        if (idx < 0)      idx = -idx;
        if (idx >= t_in)  idx = 2 * t_in - 2 - idx;
        s[i] = src[idx];
    }
    __syncthreads();

    int k = k0 + threadIdx.x;
    if (k < t_out) {
        float alo = 0.f, ahi = 0.f;
        int base = 2 * threadIdx.x;
        #pragma unroll
        for (int i = 0; i < FLEN; i++) {
            float v = s[base + i];
            alo = fmaf(v, c_lo[i], alo);
            ahi = fmaf(v, c_hi[i], ahi);
        }
        int b = row / n_in;
        int node = row - b * n_in;
        long long obase = ((long long)b * (2 * n_in) + 2 * node) * t_out + k;
        out[obase]          = alo;   // low-pass child  (index 2*node)
        out[obase + t_out]  = ahi;   // high-pass child (index 2*node+1)
    }
}

// Epilogue: Gray-code permutation + log(|x|^2 + 1e-12) and sign planes.
__global__ void finalize_kernel(int in_sel, float* __restrict__ out, int total) {
    const float* nodes = (in_sel == 1) ? g_bufA : g_bufB;
    int i = blockIdx.x * blockDim.x + threadIdx.x;
    if (i >= total) return;
    int k  = i % T8;
    int bp = i / T8;
    int p  = bp & (NNODES - 1);
    int b  = bp >> 8;
    int j  = p ^ (p >> 1);                     // Gray code: natural node index
    float x = nodes[((long long)((b << 8) | j)) * T8 + k];
    float lg = logf(fmaf(x, x, 1e-12f));
    float sg = (x < 0.f) ? -1.f : 1.f;
    long long ob = ((long long)b * 2 * NNODES + p) * T8 + k;   // plane 0
    out[ob]                              = lg;
    out[ob + (long long)NNODES * T8]     = sg;                 // plane 1
}

extern "C" void kernel_launch(void* const* d_in, const int* in_sizes, int n_in_args,
                              void* d_out, int out_size) {
    (void)in_sizes; (void)n_in_args; (void)out_size;
    const float* in0 = (const float*)d_in[0];
    float* out = (float*)d_out;

    int t = 262144;
    int n = 1;
    int cur_sel = 0;                 // external input
    for (int lev = 0; lev < 8; lev++) {
        int t_out = (t + 15) / 2;
        int out_sel = (lev % 2 == 0) ? 1 : 2;     // A,B,A,B,... -> level 8 in B
        dim3 grid((t_out + TILE - 1) / TILE, BATCH * n);
        dwt_level_kernel<<<grid, TILE>>>(in0, cur_sel, out_sel, n, t, t_out);
        cur_sel = out_sel;
        t = t_out;
        n *= 2;
    }
    // cur_sel == 2 (g_bufB), t == 1038, nodes per batch == 256
    int total = BATCH * NNODES * T8;
    finalize_kernel<<<(total + 255) / 256, 256>>>(cur_sel, out, total);
}

// round 3
// speedup vs baseline: 1.7259x; 1.7259x over previous
#include <cuda_runtime.h>

#define FLEN    16
#define BATCH   64
#define OPB     1024          // outputs per block (per child row)
#define THREADS 256
#define KPT     4
#define SWINDOW 2068          // floats loaded per block: covers s[-2 .. 2065]
#define T8      1038
#define NN8     256

// Largest scratch level is L7: 64*128*2064 = 16,908,288 floats.
#define BUF_ELEMS 16908288
__device__ float g_bufA[BUF_ELEMS];
__device__ float g_bufB[BUF_ELEMS];

// Reversed db8 filters as compile-time literals (enables FFMA-imm, rt=1).
#define DECL_FILTERS \
    constexpr float LO[16] = { \
         0.0018899503327594609f, -0.0003029205147213668f, -0.01495225833704823f, \
         0.003808752013890615f,   0.049137179673607506f,  -0.027219029917056003f, \
        -0.05194583810770904f,    0.3644418948353314f,     0.7771857517005235f, \
         0.4813596512583722f,    -0.061273359067658524f,  -0.1432942383508097f, \
         0.007607487324917605f,   0.03169508781149298f,   -0.0005421323317911481f, \
        -0.0033824159510061256f }; \
    constexpr float HI[16] = { \
        -0.0033824159510061256f,  0.0005421323317911481f,  0.03169508781149298f, \
        -0.007607487324917605f,  -0.1432942383508097f,     0.061273359067658524f, \
         0.4813596512583722f,    -0.7771857517005235f,     0.3644418948353314f, \
         0.05194583810770904f,   -0.027219029917056003f,  -0.049137179673607506f, \
         0.003808752013890615f,   0.01495225833704823f,   -0.0003029205147213668f, \
        -0.0018899503327594609f };

// Load the block's padded input window into smem.
// sraw[idx] holds signal value at index (jbase - 2 + idx), reflect-padded.
__device__ __forceinline__ void load_window(float* sraw, const float* __restrict__ src,
                                            int jbase, int t_in) {
    int a = jbase - 2;                           // multiple of 16 for interior blocks
    if (a >= 0 && a + SWINDOW <= t_in) {
        const float4* g  = (const float4*)(src + a);
        float4*       s4 = (float4*)sraw;
        #pragma unroll 3
        for (int q = threadIdx.x; q < SWINDOW / 4; q += THREADS) s4[q] = g[q];
    } else {
        for (int idx = threadIdx.x; idx < SWINDOW; idx += THREADS) {
            int m = a + idx;
            if (m < 0)      m = -m;
            if (m >= t_in)  m = 2 * t_in - 2 - m;
            sraw[idx] = src[m];
        }
    }
}

__device__ __forceinline__ void conv4(const float* w, float* lo, float* hi) {
    DECL_FILTERS
    #pragma unroll
    for (int q = 0; q < KPT; q++) {
        float a = 0.f, b = 0.f;
        #pragma unroll
        for (int i = 0; i < FLEN; i++) {
            float v = w[2 * q + i];
            a = fmaf(v, LO[i], a);
            b = fmaf(v, HI[i], b);
        }
        lo[q] = a; hi[q] = b;
    }
}

// One DWT level (levels 1..7 of the tree). in_sel: 0=ext,1=A,2=B. out_sel: 1=A,2=B.
__global__ void __launch_bounds__(THREADS)
dwt_level(const float* __restrict__ ext_in, int in_sel, int out_sel, int lev,
          int t_in, int stride_in, int t_out, int stride_out) {
    __shared__ float sraw[SWINDOW];

    const float* in  = (in_sel == 0) ? ext_in : (in_sel == 1 ? g_bufA : g_bufB);
    float*       out = (out_sel == 1) ? g_bufA : g_bufB;

    int row = blockIdx.y;                        // 0 .. BATCH*2^lev - 1
    int k0  = blockIdx.x * OPB;
    const float* src = in + (size_t)row * stride_in;

    load_window(sraw, src, 2 * k0 - 14, t_in);
    __syncthreads();

    int ko = k0 + threadIdx.x * KPT;
    if (ko >= t_out) return;

    float w[2 * KPT + FLEN - 2];
    const float* sp = sraw + 2 + 8 * threadIdx.x;
    #pragma unroll
    for (int i = 0; i < 2 * KPT + FLEN - 2; i++) w[i] = sp[i];

    float lo[KPT], hi[KPT];
    conv4(w, lo, hi);

    int b    = row >> lev;
    int node = row & ((1 << lev) - 1);
    float* olo = out + ((size_t)((b << (lev + 1)) + 2 * node)) * stride_out + ko;
    float* ohi = olo + stride_out;

    if (ko + KPT <= t_out) {
        *(float4*)olo = make_float4(lo[0], lo[1], lo[2], lo[3]);
        *(float4*)ohi = make_float4(hi[0], hi[1], hi[2], hi[3]);
    } else {
        for (int q = 0; q < t_out - ko; q++) { olo[q] = lo[q]; ohi[q] = hi[q]; }
    }
}

__device__ __forceinline__ int igray(int j) {   // inverse Gray code (8 bit)
    j ^= j >> 1; j ^= j >> 2; j ^= j >> 4; return j;
}

// Final level (7 -> 8) fused with Gray permutation + log/sign epilogue.
// Reads L7 from in_sel buffer, writes (64, 2, 256, 1038) directly.
__global__ void __launch_bounds__(THREADS)
dwt_final(int in_sel, float* __restrict__ out,
          int t_in, int stride_in, int t_out) {
    __shared__ float sraw[SWINDOW];
    const float* in = (in_sel == 1) ? g_bufA : g_bufB;

    int row = blockIdx.y;                        // 0 .. BATCH*128 - 1
    int k0  = blockIdx.x * OPB;
    const float* src = in + (size_t)row * stride_in;

    load_window(sraw, src, 2 * k0 - 14, t_in);
    __syncthreads();

    int ko = k0 + threadIdx.x * KPT;
    if (ko >= t_out) return;

    float w[2 * KPT + FLEN - 2];
    const float* sp = sraw + 2 + 8 * threadIdx.x;
    #pragma unroll
    for (int i = 0; i < 2 * KPT + FLEN - 2; i++) w[i] = sp[i];

    float lo[KPT], hi[KPT];
    conv4(w, lo, hi);

    int b    = row >> 7;
    int node = row & 127;
    int plo  = igray(2 * node);
    int phi  = igray(2 * node + 1);

    size_t base_b = (size_t)b * 2 * NN8 * T8;
    float* Llo = out + base_b + (size_t)plo * T8 + ko;      // log plane, lo child
    float* Lhi = out + base_b + (size_t)phi * T8 + ko;      // log plane, hi child
    float* Slo = Llo + (size_t)NN8 * T8;                    // sign plane
    float* Shi = Lhi + (size_t)NN8 * T8;

    int nq = (ko + KPT <= t_out) ? KPT : (t_out - ko);
    #pragma unroll
    for (int q = 0; q < KPT; q++) {
        if (q < nq) {
            float x = lo[q];
            Llo[q] = logf(fmaf(x, x, 1e-12f));
            Slo[q] = (x < 0.f) ? -1.f : 1.f;
            float y = hi[q];
            Lhi[q] = logf(fmaf(y, y, 1e-12f));
            Shi[q] = (y < 0.f) ? -1.f : 1.f;
        }
    }
}

extern "C" void kernel_launch(void* const* d_in, const int* in_sizes, int n_in_args,
                              void* d_out, int out_size) {
    (void)in_sizes; (void)n_in_args; (void)out_size;
    const float* in0 = (const float*)d_in[0];
    float* out = (float*)d_out;

    int t = 262144, stride = 262144;
    int cur_sel = 0;
    // Levels 1..7
    for (int lev = 0; lev < 7; lev++) {
        int t_out = (t + 15) / 2;
        int stride_out = (t_out + 3) & ~3;
        int out_sel = (lev % 2 == 0) ? 1 : 2;    // A,B,A,B,A,B,A -> L7 in A
        dim3 grid((t_out + OPB - 1) / OPB, BATCH << lev);
        dwt_level<<<grid, THREADS>>>(in0, cur_sel, out_sel, lev,
                                     t, stride, t_out, stride_out);
        cur_sel = out_sel;
        t = t_out; stride = stride_out;
    }
    // Level 8 fused with permutation + log/sign epilogue. t==2062, stride==2064.
    dim3 gridF((T8 + OPB - 1) / OPB, BATCH << 7);
    dwt_final<<<gridF, THREADS>>>(cur_sel, out, t, stride, T8);
}

// round 6
// speedup vs baseline: 2.1632x; 1.2534x over previous
#include <cuda_runtime.h>

#define K       512           // level-B outputs per block per grandchild row
#define THREADS 256
#define KA      5             // level-A outputs per thread
#define FLEN    16
#define BATCH   64
#define T8      1038
#define NN8     256

// Largest scratch buffer: L6 = 4096 rows x 4112 stride = 16,842,752 floats.
#define BUF_ELEMS 16842752
__device__ float g_bufA[BUF_ELEMS];
__device__ float g_bufB[BUF_ELEMS];

// Reversed db8 filters as compile-time literals (FFMA-imm form, rt=1).
#define DECL_FILTERS \
    constexpr float LO[16] = { \
         0.0018899503327594609f, -0.0003029205147213668f, -0.01495225833704823f, \
         0.003808752013890615f,   0.049137179673607506f,  -0.027219029917056003f, \
        -0.05194583810770904f,    0.3644418948353314f,     0.7771857517005235f, \
         0.4813596512583722f,    -0.061273359067658524f,  -0.1432942383508097f, \
         0.007607487324917605f,   0.03169508781149298f,   -0.0005421323317911481f, \
        -0.0033824159510061256f }; \
    constexpr float HI[16] = { \
        -0.0033824159510061256f,  0.0005421323317911481f,  0.03169508781149298f, \
        -0.007607487324917605f,  -0.1432942383508097f,     0.061273359067658524f, \
         0.4813596512583722f,    -0.7771857517005235f,     0.3644418948353314f, \
         0.05194583810770904f,   -0.027219029917056003f,  -0.049137179673607506f, \
         0.003808752013890615f,   0.01495225833704823f,   -0.0003029205147213668f, \
        -0.0018899503327594609f };

template<int Q>
__device__ __forceinline__ void convN(const float* w, float* lo, float* hi) {
    DECL_FILTERS
    #pragma unroll
    for (int q = 0; q < Q; q++) {
        float a = 0.f, b = 0.f;
        #pragma unroll
        for (int i = 0; i < FLEN; i++) {
            float v = w[2 * q + i];
            a = fmaf(v, LO[i], a);
            b = fmaf(v, HI[i], b);
        }
        lo[q] = a; hi[q] = b;
    }
}

__device__ __forceinline__ int igray(int j) { j ^= j >> 1; j ^= j >> 2; j ^= j >> 4; return j; }

// Fused two-level DWT. Input: rows at level `lev` (BATCH<<lev rows, length t_in).
// Produces level lev+2 (grandchildren). IS_FINAL fuses the Gray-permute +
// log/sign epilogue (lev==6 -> level 8 -> d_out).
template<int IS_FINAL>
__global__ void __launch_bounds__(THREADS)
dwt_pair(const float* __restrict__ ext_in, int in_sel, int out_sel, int lev,
         int t_in, int stride_in, int t_outA, int t_outB, int stride_out,
         float* __restrict__ fout)
{
    __shared__ float s_in[2104];     // input window (+slack for aligned reg loads)
    __shared__ float s_lo[1040];     // level-A low-pass child tile
    __shared__ float s_hi[1040];     // level-A high-pass child tile

    const float* in  = (in_sel == 0) ? ext_in : ((in_sel == 1) ? g_bufA : g_bufB);
    float*       outb = (out_sel == 1) ? g_bufA : g_bufB;

    int row = blockIdx.y;
    int k0  = blockIdx.x * K;
    const float* src = in + (size_t)row * stride_in;

    // Level-A index range needed by this block's level-B outputs.
    int mstart = 2 * k0 - 14;           if (mstart < 0) mstart = 0;
    int mend   = 2 * k0 + 2 * K - 1;    if (mend > t_outA - 1) mend = t_outA - 1;
    int aa = 2 * mstart - 16;           // s_in[idx] = x[reflect(aa+idx)]
    bool interior = (2 * k0 - 14 >= 0) && (2 * k0 + 2 * K - 1 <= t_outA - 1);

    // ---- load input window ----
    if (interior && aa >= 0 && aa + 2092 <= t_in) {
        const float4* g  = (const float4*)(src + aa);    // aa = 4*k0-44, 16B aligned
        float4*       s4 = (float4*)s_in;
        #pragma unroll
        for (int q = threadIdx.x; q < 523; q += THREADS) s4[q] = g[q];
    } else {
        int nload = 2 * mend + 2 - aa;
        for (int idx = threadIdx.x; idx < nload; idx += THREADS) {
            int m = aa + idx;
            if (m < 0)      m = -m;
            if (m >= t_in)  m = 2 * t_in - 2 - m;
            s_in[idx] = src[m];
        }
    }
    __syncthreads();

    // ---- level A: compute child rows into smem ----
    {
        int m0 = mstart + threadIdx.x * KA;
        if (m0 <= mend) {
            int cnt = mend - m0 + 1; if (cnt > KA) cnt = KA;
            int base = 2 * (m0 - mstart) + 2;       // s_in offset of first tap
            int ab   = base & ~3;
            float4 w4[7];
            const float4* sp4 = (const float4*)(s_in + ab);
            #pragma unroll
            for (int i = 0; i < 7; i++) w4[i] = sp4[i];
            const float* w = (const float*)w4 + (base - ab);
            float lo[KA], hi[KA];
            convN<KA>(w, lo, hi);
            #pragma unroll
            for (int q = 0; q < KA; q++)
                if (q < cnt) { s_lo[m0 - mstart + q] = lo[q]; s_hi[m0 - mstart + q] = hi[q]; }
        }
    }
    __syncthreads();

    // ---- level B: 4 outputs per thread; threads [0,128) child0, [128,256) child1 ----
    int c  = threadIdx.x >> 7;
    int kk = k0 + (threadIdx.x & 127) * 4;
    if (kk >= t_outB) return;

    const float* sA = c ? s_hi : s_lo;
    float4 wv[6];
    float* w = (float*)wv;
    if (interior) {
        int base = 2 * (kk - k0);                   // multiple of 8 -> aligned LDS.128
        const float4* sp4 = (const float4*)(sA + base);
        #pragma unroll
        for (int i = 0; i < 6; i++) wv[i] = sp4[i];
    } else {
        #pragma unroll
        for (int i = 0; i < 22; i++) {
            int m = 2 * kk - 14 + i;
            if (m < 0)       m = -m;
            if (m >= t_outA) m = 2 * t_outA - 2 - m;
            w[i] = sA[m - mstart];
        }
    }
    float lo2[4], hi2[4];
    convN<4>(w, lo2, hi2);

    if (!IS_FINAL) {
        int b    = row >> lev;
        int node = row & ((1 << lev) - 1);
        size_t r = ((size_t)((b << (lev + 2)) + 4 * node + 2 * c)) * stride_out + kk;
        if (kk + 4 <= t_outB) {
            *(float4*)(outb + r)              = make_float4(lo2[0], lo2[1], lo2[2], lo2[3]);
            *(float4*)(outb + r + stride_out) = make_float4(hi2[0], hi2[1], hi2[2], hi2[3]);
        } else {
            for (int q = 0; q < t_outB - kk; q++) {
                outb[r + q]              = lo2[q];
                outb[r + stride_out + q] = hi2[q];
            }
        }
    } else {
        int b    = row >> 6;
        int node = row & 63;
        int p0 = igray(4 * node + 2 * c);
        int p1 = igray(4 * node + 2 * c + 1);
        size_t ob   = (size_t)b * (2 * NN8 * T8);
        const size_t SOFF = (size_t)NN8 * T8;
        float* L0 = fout + ob + (size_t)p0 * T8 + kk;
        float* L1 = fout + ob + (size_t)p1 * T8 + kk;
        if (kk + 4 <= t_outB) {
            *(float2*)(L0)            = make_float2(logf(fmaf(lo2[0], lo2[0], 1e-12f)),
                                                    logf(fmaf(lo2[1], lo2[1], 1e-12f)));
            *(float2*)(L0 + 2)        = make_float2(logf(fmaf(lo2[2], lo2[2], 1e-12f)),
                                                    logf(fmaf(lo2[3], lo2[3], 1e-12f)));
            *(float2*)(L0 + SOFF)     = make_float2(lo2[0] < 0.f ? -1.f : 1.f,
                                                    lo2[1] < 0.f ? -1.f : 1.f);
            *(float2*)(L0 + SOFF + 2) = make_float2(lo2[2] < 0.f ? -1.f : 1.f,
                                                    lo2[3] < 0.f ? -1.f : 1.f);
            *(float2*)(L1)            = make_float2(logf(fmaf(hi2[0], hi2[0], 1e-12f)),
                                                    logf(fmaf(hi2[1], hi2[1], 1e-12f)));
            *(float2*)(L1 + 2)        = make_float2(logf(fmaf(hi2[2], hi2[2], 1e-12f)),
                                                    logf(fmaf(hi2[3], hi2[3], 1e-12f)));
            *(float2*)(L1 + SOFF)     = make_float2(hi2[0] < 0.f ? -1.f : 1.f,
                                                    hi2[1] < 0.f ? -1.f : 1.f);
            *(float2*)(L1 + SOFF + 2) = make_float2(hi2[2] < 0.f ? -1.f : 1.f,
                                                    hi2[3] < 0.f ? -1.f : 1.f);
        } else {
            for (int q = 0; q < t_outB - kk; q++) {
                float x = lo2[q], y = hi2[q];
                L0[q]        = logf(fmaf(x, x, 1e-12f));
                L0[SOFF + q] = (x < 0.f) ? -1.f : 1.f;
                L1[q]        = logf(fmaf(y, y, 1e-12f));
                L1[SOFF + q] = (y < 0.f) ? -1.f : 1.f;
            }
        }
    }
}

extern "C" void kernel_launch(void* const* d_in, const int* in_sizes, int n_in_args,
                              void* d_out, int out_size) {
    (void)in_sizes; (void)n_in_args; (void)out_size;
    const float* in0 = (const float*)d_in[0];
    float* out = (float*)d_out;

    // t chain: 262144 -> 131079 -> 65547 -> 32781 -> 16398 -> 8206 -> 4110 -> 2062 -> 1038
    dim3 g0((65547 + K - 1) / K, 64);      // ext -> L2 (bufA)
    dwt_pair<0><<<g0, THREADS>>>(in0, 0, 1, 0, 262144, 262144, 131079, 65547, 65548, nullptr);
    dim3 g1((16398 + K - 1) / K, 256);     // L2 -> L4 (bufB)
    dwt_pair<0><<<g1, THREADS>>>(in0, 1, 2, 2, 65547, 65548, 32781, 16398, 16400, nullptr);
    dim3 g2((4110 + K - 1) / K, 1024);     // L4 -> L6 (bufA)
    dwt_pair<0><<<g2, THREADS>>>(in0, 2, 1, 4, 16398, 16400, 8206, 4110, 4112, nullptr);
    dim3 g3((1038 + K - 1) / K, 4096);     // L6 -> L8 + epilogue -> out
    dwt_pair<1><<<g3, THREADS>>>(in0, 1, 0, 6, 4110, 4112, 2062, 1038, 0, out);
}

// round 7
// speedup vs baseline: 3.7387x; 1.7283x over previous
#include <cuda_runtime.h>

#define K       512
#define THREADS 256
#define KA      5
#define FLEN    16
#define T8      1038
#define NN8     256

#define BUF_ELEMS 16842752
__device__ float g_bufA[BUF_ELEMS];
__device__ float g_bufB[BUF_ELEMS];

#define DECL_FILTERS \
    constexpr float LO[16] = { \
         0.0018899503327594609f, -0.0003029205147213668f, -0.01495225833704823f, \
         0.003808752013890615f,   0.049137179673607506f,  -0.027219029917056003f, \
        -0.05194583810770904f,    0.3644418948353314f,     0.7771857517005235f, \
         0.4813596512583722f,    -0.061273359067658524f,  -0.1432942383508097f, \
         0.007607487324917605f,   0.03169508781149298f,   -0.0005421323317911481f, \
        -0.0033824159510061256f }; \
    constexpr float HI[16] = { \
        -0.0033824159510061256f,  0.0005421323317911481f,  0.03169508781149298f, \
        -0.007607487324917605f,  -0.1432942383508097f,     0.061273359067658524f, \
         0.4813596512583722f,    -0.7771857517005235f,     0.3644418948353314f, \
         0.05194583810770904f,   -0.027219029917056003f,  -0.049137179673607506f, \
         0.003808752013890615f,   0.01495225833704823f,   -0.0003029205147213668f, \
        -0.0018899503327594609f };

template<int Q>
__device__ __forceinline__ void convN(const float* w, float* lo, float* hi) {
    DECL_FILTERS
    #pragma unroll
    for (int q = 0; q < Q; q++) {
        float a = 0.f, b = 0.f;
        #pragma unroll
        for (int i = 0; i < FLEN; i++) {
            float v = w[2 * q + i];
            a = fmaf(v, LO[i], a);
            b = fmaf(v, HI[i], b);
        }
        lo[q] = a; hi[q] = b;
    }
}

__device__ __forceinline__ int igray(int j) { j ^= j >> 1; j ^= j >> 2; j ^= j >> 4; return j; }

// ---------------- Mid kernel: two fused DWT levels, tiled ----------------
__global__ void __launch_bounds__(THREADS)
dwt_pair_mid(const float* __restrict__ ext_in, int in_sel, int out_sel, int lev,
             int t_in, int stride_in, int t_outA, int t_outB, int stride_out)
{
    __shared__ float s_in[2104];
    __shared__ float s_lo[1040];
    __shared__ float s_hi[1040];

    const float* in  = (in_sel == 0) ? ext_in : ((in_sel == 1) ? g_bufA : g_bufB);
    float*       outb = (out_sel == 1) ? g_bufA : g_bufB;

    int row = blockIdx.y;
    int k0  = blockIdx.x * K;
    const float* src = in + (size_t)row * stride_in;

    int mstart = 2 * k0 - 14;           if (mstart < 0) mstart = 0;
    int mend   = 2 * k0 + 2 * K - 1;    if (mend > t_outA - 1) mend = t_outA - 1;
    int aa = 2 * mstart - 16;
    bool interior = (2 * k0 - 14 >= 0) && (2 * k0 + 2 * K - 1 <= t_outA - 1);

    // ---- input window ----
    if (interior && aa >= 0 && aa + 2092 <= t_in) {
        const float4* g  = (const float4*)(src + aa);
        float4*       s4 = (float4*)s_in;
        #pragma unroll
        for (int q = threadIdx.x; q < 523; q += THREADS) s4[q] = g[q];
    } else {
        int nload = 2 * mend + 2 - aa;
        for (int idx = threadIdx.x; idx < nload; idx += THREADS) {
            int m = aa + idx;
            if (m < 0)      m = -m;
            if (m >= t_in)  m = 2 * t_in - 2 - m;
            s_in[idx] = src[m];
        }
    }
    __syncthreads();

    // ---- level A: scalar LDS, compile-time indices only (no spill) ----
    {
        int m0 = mstart + threadIdx.x * KA;
        if (m0 <= mend) {
            int cnt = mend - m0 + 1; if (cnt > KA) cnt = KA;
            const float* sp = s_in + 2 * (m0 - mstart) + 2;
            float w[2 * KA + FLEN - 2];
            #pragma unroll
            for (int i = 0; i < 2 * KA + FLEN - 2; i++) w[i] = sp[i];
            float lo[KA], hi[KA];
            convN<KA>(w, lo, hi);
            #pragma unroll
            for (int q = 0; q < KA; q++)
                if (q < cnt) { s_lo[m0 - mstart + q] = lo[q]; s_hi[m0 - mstart + q] = hi[q]; }
        }
    }
    __syncthreads();

    // ---- level B ----
    int c  = threadIdx.x >> 7;
    int kk = k0 + (threadIdx.x & 127) * 4;
    if (kk >= t_outB) return;

    const float* sA = c ? s_hi : s_lo;
    float w[22];
    if (interior) {
        float4 wv[6];
        const float4* sp4 = (const float4*)(sA + 2 * (kk - k0));   // multiple of 8 floats
        #pragma unroll
        for (int i = 0; i < 6; i++) wv[i] = sp4[i];
        const float* wf = (const float*)wv;
        #pragma unroll
        for (int i = 0; i < 22; i++) w[i] = wf[i];
    } else {
        #pragma unroll
        for (int i = 0; i < 22; i++) {
            int m = 2 * kk - 14 + i;
            if (m < 0)       m = -m;
            if (m >= t_outA) m = 2 * t_outA - 2 - m;
            w[i] = sA[m - mstart];
        }
    }
    float lo2[4], hi2[4];
    convN<4>(w, lo2, hi2);

    int b    = row >> lev;
    int node = row & ((1 << lev) - 1);
    size_t r = ((size_t)((b << (lev + 2)) + 4 * node + 2 * c)) * stride_out + kk;
    if (kk + 4 <= t_outB) {
        *(float4*)(outb + r)              = make_float4(lo2[0], lo2[1], lo2[2], lo2[3]);
        *(float4*)(outb + r + stride_out) = make_float4(hi2[0], hi2[1], hi2[2], hi2[3]);
    } else {
        for (int q = 0; q < t_outB - kk; q++) {
            outb[r + q]              = lo2[q];
            outb[r + stride_out + q] = hi2[q];
        }
    }
}

// ---------------- Final kernel: whole L6 row -> L8 + permute/log/sign ----------------
// Input: g_bufA rows of length 4110 (stride 4112). One block per row (4096 rows).
__global__ void __launch_bounds__(THREADS)
dwt_final_row(float* __restrict__ out)
{
    __shared__ float s_in[4112];
    __shared__ float s_lo[2064];
    __shared__ float s_hi[2064];

    int row = blockIdx.x;                       // 0..4095
    const float* src = g_bufA + (size_t)row * 4112;

    {   // load full row (stride-padded, so reading 1028 float4 is in-bounds)
        const float4* g4 = (const float4*)src;
        float4* s4 = (float4*)s_in;
        #pragma unroll
        for (int q = threadIdx.x; q < 1028; q += THREADS) s4[q] = g4[q];
    }
    __syncthreads();

    // ---- level A: t 4110 -> 2062 ----
    for (int m0 = threadIdx.x * 4; m0 < 2062; m0 += 4 * THREADS) {
        int cnt = 2062 - m0; if (cnt > 4) cnt = 4;
        int jb = 2 * m0 - 14;
        float w[22];
        if (jb >= 0 && jb + 21 <= 4109) {
            float4 wv[6];
            const float4* sp4 = (const float4*)(s_in + (jb - 2));  // jb-2 = 8*tid-16, aligned
            #pragma unroll
            for (int i = 0; i < 6; i++) wv[i] = sp4[i];
            const float* wf = (const float*)wv;
            #pragma unroll
            for (int i = 0; i < 22; i++) w[i] = wf[i + 2];
        } else {
            #pragma unroll
            for (int i = 0; i < 22; i++) {
                int m = jb + i;
                if (m < 0)     m = -m;
                if (m >= 4110) m = 2 * 4110 - 2 - m;
                w[i] = s_in[m];
            }
        }
        float lo[4], hi[4];
        convN<4>(w, lo, hi);
        if (cnt == 4) {
            *(float4*)(s_lo + m0) = make_float4(lo[0], lo[1], lo[2], lo[3]);
            *(float4*)(s_hi + m0) = make_float4(hi[0], hi[1], hi[2], hi[3]);
        } else {
            for (int q = 0; q < cnt; q++) { s_lo[m0 + q] = lo[q]; s_hi[m0 + q] = hi[q]; }
        }
    }
    __syncthreads();

    // ---- level B: t 2062 -> 1038, fused epilogue ----
    int c  = threadIdx.x >> 7;
    int tb = threadIdx.x & 127;
    const float* sA = c ? s_hi : s_lo;

    int b    = row >> 6;
    int node = row & 63;
    int p0 = igray(4 * node + 2 * c);
    int p1 = igray(4 * node + 2 * c + 1);
    size_t ob = (size_t)b * (2 * NN8 * T8);
    const size_t SOFF = (size_t)NN8 * T8;
    float* L0 = out + ob + (size_t)p0 * T8;
    float* L1 = out + ob + (size_t)p1 * T8;

    for (int k0 = tb * 4; k0 < T8; k0 += 4 * 128) {
        int cnt = T8 - k0; if (cnt > 4) cnt = 4;
        int jb = 2 * k0 - 14;
        float w[22];
        if (jb >= 0 && jb + 21 <= 2061) {
            float4 wv[6];
            const float4* sp4 = (const float4*)(sA + (jb - 2));    // aligned
            #pragma unroll
            for (int i = 0; i < 6; i++) wv[i] = sp4[i];
            const float* wf = (const float*)wv;
            #pragma unroll
            for (int i = 0; i < 22; i++) w[i] = wf[i + 2];
        } else {
            #pragma unroll
            for (int i = 0; i < 22; i++) {
                int m = jb + i;
                if (m < 0)     m = -m;
                if (m >= 2062) m = 2 * 2062 - 2 - m;
                w[i] = sA[m];
            }
        }
        float lo2[4], hi2[4];
        convN<4>(w, lo2, hi2);

        if (cnt == 4) {
            *(float2*)(L0 + k0)        = make_float2(__logf(fmaf(lo2[0], lo2[0], 1e-12f)),
                                                     __logf(fmaf(lo2[1], lo2[1], 1e-12f)));
            *(float2*)(L0 + k0 + 2)    = make_float2(__logf(fmaf(lo2[2], lo2[2], 1e-12f)),
                                                     __logf(fmaf(lo2[3], lo2[3], 1e-12f)));
            *(float2*)(L0 + SOFF + k0)     = make_float2(lo2[0] < 0.f ? -1.f : 1.f,
                                                         lo2[1] < 0.f ? -1.f : 1.f);
            *(float2*)(L0 + SOFF + k0 + 2) = make_float2(lo2[2] < 0.f ? -1.f : 1.f,
                                                         lo2[3] < 0.f ? -1.f : 1.f);
            *(float2*)(L1 + k0)        = make_float2(__logf(fmaf(hi2[0], hi2[0], 1e-12f)),
                                                     __logf(fmaf(hi2[1], hi2[1], 1e-12f)));
            *(float2*)(L1 + k0 + 2)    = make_float2(__logf(fmaf(hi2[2], hi2[2], 1e-12f)),
                                                     __logf(fmaf(hi2[3], hi2[3], 1e-12f)));
            *(float2*)(L1 + SOFF + k0)     = make_float2(hi2[0] < 0.f ? -1.f : 1.f,
                                                         hi2[1] < 0.f ? -1.f : 1.f);
            *(float2*)(L1 + SOFF + k0 + 2) = make_float2(hi2[2] < 0.f ? -1.f : 1.f,
                                                         hi2[3] < 0.f ? -1.f : 1.f);
        } else {
            for (int q = 0; q < cnt; q++) {
                float x = lo2[q], y = hi2[q];
                L0[k0 + q]        = __logf(fmaf(x, x, 1e-12f));
                L0[SOFF + k0 + q] = (x < 0.f) ? -1.f : 1.f;
                L1[k0 + q]        = __logf(fmaf(y, y, 1e-12f));
                L1[SOFF + k0 + q] = (y < 0.f) ? -1.f : 1.f;
            }
        }
    }
}

extern "C" void kernel_launch(void* const* d_in, const int* in_sizes, int n_in_args,
                              void* d_out, int out_size) {
    (void)in_sizes; (void)n_in_args; (void)out_size;
    const float* in0 = (const float*)d_in[0];
    float* out = (float*)d_out;

    // t chain: 262144 -> 131079 -> 65547 -> 32781 -> 16398 -> 8206 -> 4110 -> 2062 -> 1038
    dim3 g0((65547 + K - 1) / K, 64);      // ext -> L2 (bufA)
    dwt_pair_mid<<<g0, THREADS>>>(in0, 0, 1, 0, 262144, 262144, 131079, 65547, 65548);
    dim3 g1((16398 + K - 1) / K, 256);     // L2 -> L4 (bufB)
    dwt_pair_mid<<<g1, THREADS>>>(in0, 1, 2, 2, 65547, 65548, 32781, 16398, 16400);
    dim3 g2((4110 + K - 1) / K, 1024);     // L4 -> L6 (bufA)
    dwt_pair_mid<<<g2, THREADS>>>(in0, 2, 1, 4, 16398, 16400, 8206, 4110, 4112);
    // L6 -> L8 + permute/log/sign, one block per L6 row
    dwt_final_row<<<4096, THREADS>>>(out);
}